// round 12
// baseline (speedup 1.0000x reference)
#include <cuda_runtime.h>
#include <cuda_bf16.h>
#include <cstdint>

// out[e*12 + 0..11] = W[h][rel_pos[e]]  -> gather of W^T rows.
// R8: R3-winning structure (16KB tiles, 256 thr, 2 buffers, 8 tiles/CTA)
// + L2::cache_hint evict_first on the bulk stores: output is write-once,
// never re-read, so mark its L2 lines evict-first to speed DRAM drain and
// keep L2 capacity for the rel_pos read stream.

#define THREADS       256
#define F4_PER_THREAD 4
#define TILE_F4       (THREADS * F4_PER_THREAD)   // 1024 float4 = 16 KB
#define TILES_PER_CTA 8                           // 128 KB contiguous per CTA

__device__ __forceinline__ unsigned smem_u32(const void* p) {
    unsigned a;
    asm("{ .reg .u64 x; cvta.to.shared.u64 x, %1; cvt.u32.u64 %0, x; }"
        : "=r"(a) : "l"(p));
    return a;
}

__global__ __launch_bounds__(THREADS)
void gather_wt_r8(const int* __restrict__ rel_pos,
                  const float* __restrict__ W,       // [12,64]
                  float4* __restrict__ out4)
{
    __shared__ __align__(16)  float4 table4[64 * 3];        // table4[cls*3+c]
    __shared__ __align__(128) float4 stage4[2][TILE_F4];    // 2 x 16 KB

    float* table = reinterpret_cast<float*>(table4);
    unsigned t = threadIdx.x;

    // Transposed table: table[c*12 + h] = W[h*64 + c]
    #pragma unroll
    for (int i = 0; i < 3; i++) {
        unsigned j = t + i * 256u;           // [0,768)
        table[(j & 63u) * 12u + (j >> 6)] = W[j];
    }
    __syncthreads();

    // Evict-first policy for the streaming output writes.
    unsigned long long pol;
    asm volatile("createpolicy.fractional.L2::evict_first.b64 %0, 1.0;" : "=l"(pol));

    unsigned tile0 = blockIdx.x * (unsigned)TILES_PER_CTA;

    #pragma unroll
    for (int it = 0; it < TILES_PER_CTA; it++) {
        int buf = it & 1;
        unsigned base = (tile0 + (unsigned)it) * (unsigned)TILE_F4;

        // Reuse gate: wait only until the older bulk store finished READING smem.
        if (it >= 2) {
            if (t == 0)
                asm volatile("cp.async.bulk.wait_group.read 1;" ::: "memory");
            __syncthreads();
        }

        // Gather: linear STS (conflict-free); random-row LDS from table.
        #pragma unroll
        for (int k = 0; k < F4_PER_THREAD; k++) {
            unsigned j = base + t + k * 256u;    // output float4 index
            unsigned e = j / 3u;                 // element
            unsigned c = j - e * 3u;             // chunk 0..2
            int cls = rel_pos[e];                // adjacent lanes merge in L1
            stage4[buf][t + k * 256u] = table4[(unsigned)cls * 3u + c];
        }
        __syncthreads();

        // Async bulk store with evict-first L2 hint: 16 KB smem -> gmem.
        if (t == 0) {
            unsigned saddr = smem_u32(stage4[buf]);
            unsigned long long gaddr = (unsigned long long)(out4 + base);
            asm volatile("fence.proxy.async;" ::: "memory");
            asm volatile(
                "cp.async.bulk.global.shared::cta.bulk_group.L2::cache_hint"
                " [%0], [%1], %2, %3;"
                :: "l"(gaddr), "r"(saddr), "n"(TILE_F4 * 16), "l"(pol) : "memory");
            asm volatile("cp.async.bulk.commit_group;" ::: "memory");
        }
        // Buffer untouched until its read-wait above; no extra sync needed.
    }

    // Full drain before CTA exit (global visibility + smem handoff).
    if (t == 0)
        asm volatile("cp.async.bulk.wait_group 0;" ::: "memory");
    __syncthreads();
}

// Generic tail (unused for the benchmark shapes): direct gather + store.
__global__ __launch_bounds__(256)
void gather_wt_tail(const int* __restrict__ rel_pos,
                    const float* __restrict__ W,
                    float4* __restrict__ out4,
                    unsigned start, unsigned n4)
{
    __shared__ float4 table4[64 * 3];
    float* table = reinterpret_cast<float*>(table4);
    unsigned t = threadIdx.x;
    #pragma unroll
    for (int i = 0; i < 3; i++) {
        unsigned j = t + i * 256u;
        table[(j & 63u) * 12u + (j >> 6)] = W[j];
    }
    __syncthreads();

    unsigned j = start + blockIdx.x * 256u + t;
    if (j < n4) {
        unsigned e = j / 3u;
        unsigned c = j - e * 3u;
        int cls = rel_pos[e];
        out4[j] = table4[(unsigned)cls * 3u + c];
    }
}

extern "C" void kernel_launch(void* const* d_in, const int* in_sizes, int n_in,
                              void* d_out, int out_size)
{
    const int*   rel_pos = (const int*)d_in[0];    // [4,2048,2048] int32
    // d_in[1] = hidden_states (unused; dtype carrier only)
    const float* W       = (const float*)d_in[2];  // [12,64] float32
    float4*      out4    = (float4*)d_out;

    unsigned n_elem  = (unsigned)in_sizes[0];      // 16,777,216
    unsigned n4      = n_elem * 3u;                // 50,331,648 float4
    unsigned per_cta = (unsigned)(TILE_F4 * TILES_PER_CTA);   // 8192 float4
    unsigned blocks  = n4 / per_cta;               // 6144 exact for bench
    unsigned done    = blocks * per_cta;

    if (blocks)
        gather_wt_r8<<<blocks, THREADS>>>(rel_pos, W, out4);

    if (done < n4) {
        unsigned rem = n4 - done;
        unsigned tb  = (rem + 255u) / 256u;
        gather_wt_tail<<<tb, 256>>>(rel_pos, W, out4, done, n4);
    }
}

// round 13
// speedup vs baseline: 1.0267x; 1.0267x over previous
#include <cuda_runtime.h>
#include <cuda_bf16.h>
#include <cstdint>

// out[e*12 + 0..11] = W[h][rel_pos[e]]  -> gather of W^T rows.
// FINAL (R3 config, best measured): gather into linear smem staging tiles
// (conflict-free STS.128), drain 16KB per tile via cp.async.bulk store,
// double-buffered, 4 tiles per CTA. Pinned at the DRAM write-stream ceiling
// (~6.05 TB/s for this 12:1 write:read pattern); all deeper/shallower
// pipelines, read-waits, and L2 policies measured neutral or worse.

#define THREADS       256
#define F4_PER_THREAD 4
#define TILE_F4       (THREADS * F4_PER_THREAD)   // 1024 float4 = 16 KB
#define TILES_PER_CTA 4

__device__ __forceinline__ unsigned smem_u32(const void* p) {
    unsigned a;
    asm("{ .reg .u64 x; cvta.to.shared.u64 x, %1; cvt.u32.u64 %0, x; }"
        : "=r"(a) : "l"(p));
    return a;
}

__global__ __launch_bounds__(THREADS)
void gather_wt_pipe(const int* __restrict__ rel_pos,
                    const float* __restrict__ W,       // [12,64]
                    float4* __restrict__ out4)
{
    __shared__ __align__(16)  float4 table4[64 * 3];        // table4[cls*3+c]
    __shared__ __align__(128) float4 stage4[2][TILE_F4];    // 2 x 16 KB

    float* table = reinterpret_cast<float*>(table4);
    unsigned t = threadIdx.x;

    // Transposed table: table[c*12 + h] = W[h*64 + c]
    #pragma unroll
    for (int i = 0; i < 3; i++) {
        unsigned j = t + i * 256u;           // [0,768)
        table[(j & 63u) * 12u + (j >> 6)] = W[j];
    }
    __syncthreads();

    unsigned tile0 = blockIdx.x * (unsigned)TILES_PER_CTA;

    #pragma unroll
    for (int it = 0; it < TILES_PER_CTA; it++) {
        int buf = it & 1;
        unsigned base = (tile0 + (unsigned)it) * (unsigned)TILE_F4;

        // Before reusing a buffer, make sure its previous bulk store drained.
        if (it >= 2) {
            if (t == 0)
                asm volatile("cp.async.bulk.wait_group 1;" ::: "memory");
            __syncthreads();
        }

        // Gather: linear STS (conflict-free), random-row LDS from table.
        #pragma unroll
        for (int k = 0; k < F4_PER_THREAD; k++) {
            unsigned j = base + t + k * 256u;    // output float4 index
            unsigned e = j / 3u;                 // element
            unsigned c = j - e * 3u;             // chunk 0..2
            int cls = rel_pos[e];                // adjacent lanes merge in L1
            stage4[buf][t + k * 256u] = table4[(unsigned)cls * 3u + c];
        }
        __syncthreads();

        // Async bulk store: 16 KB smem -> gmem.
        if (t == 0) {
            unsigned saddr = smem_u32(stage4[buf]);
            unsigned long long gaddr = (unsigned long long)(out4 + base);
            asm volatile("fence.proxy.async;" ::: "memory");
            asm volatile("cp.async.bulk.global.shared::cta.bulk_group [%0], [%1], %2;"
                         :: "l"(gaddr), "r"(saddr), "n"(TILE_F4 * 16) : "memory");
            asm volatile("cp.async.bulk.commit_group;" ::: "memory");
        }
        // Buffer untouched again until its wait above; no extra sync needed.
    }

    // Drain all outstanding stores before CTA exit (smem reuse by next CTA).
    if (t == 0)
        asm volatile("cp.async.bulk.wait_group 0;" ::: "memory");
    __syncthreads();
}

// Generic tail (unused for the benchmark shapes): direct gather + store.
__global__ __launch_bounds__(256)
void gather_wt_tail(const int* __restrict__ rel_pos,
                    const float* __restrict__ W,
                    float4* __restrict__ out4,
                    unsigned start, unsigned n4)
{
    __shared__ float4 table4[64 * 3];
    float* table = reinterpret_cast<float*>(table4);
    unsigned t = threadIdx.x;
    #pragma unroll
    for (int i = 0; i < 3; i++) {
        unsigned j = t + i * 256u;
        table[(j & 63u) * 12u + (j >> 6)] = W[j];
    }
    __syncthreads();

    unsigned j = start + blockIdx.x * 256u + t;
    if (j < n4) {
        unsigned e = j / 3u;
        unsigned c = j - e * 3u;
        int cls = rel_pos[e];
        out4[j] = table4[(unsigned)cls * 3u + c];
    }
}

extern "C" void kernel_launch(void* const* d_in, const int* in_sizes, int n_in,
                              void* d_out, int out_size)
{
    const int*   rel_pos = (const int*)d_in[0];    // [4,2048,2048] int32
    // d_in[1] = hidden_states (unused; dtype carrier only)
    const float* W       = (const float*)d_in[2];  // [12,64] float32
    float4*      out4    = (float4*)d_out;

    unsigned n_elem  = (unsigned)in_sizes[0];      // 16,777,216
    unsigned n4      = n_elem * 3u;                // 50,331,648 float4
    unsigned per_cta = (unsigned)(TILE_F4 * TILES_PER_CTA);   // 4096 float4
    unsigned blocks  = n4 / per_cta;               // 12,288 exact for bench
    unsigned done    = blocks * per_cta;

    if (blocks)
        gather_wt_pipe<<<blocks, THREADS>>>(rel_pos, W, out4);

    if (done < n4) {
        unsigned rem = n4 - done;
        unsigned tb  = (rem + 255u) / 256u;
        gather_wt_tail<<<tb, 256>>>(rel_pos, W, out4, done, n4);
    }
}

// round 14
// speedup vs baseline: 1.0308x; 1.0040x over previous
#include <cuda_runtime.h>
#include <cuda_bf16.h>
#include <cstdint>

// out[e*12 + 0..11] = W[h][rel_pos[e]]  -> gather of W^T rows.
// R9: one thread per ELEMENT (1 LDG -> 3 float4 stores), killing the j/3
// division and 2/3 of index LDGs vs the per-float4 mapping. Stride-3 STS.128
// is conflict-free (bank group 12i+4c mod 32 permutes over each 8-lane phase).
// 512 thr, 24KB tiles, 2 buffers, 8 tiles/CTA, 64 warps/SM.

#define THREADS       512
#define TILE_ELEM     (THREADS)            // 512 elements per tile
#define TILE_F4       (TILE_ELEM * 3)      // 1536 float4 = 24 KB
#define TILES_PER_CTA 8                    // 4096 elements / CTA

__device__ __forceinline__ unsigned smem_u32(const void* p) {
    unsigned a;
    asm("{ .reg .u64 x; cvta.to.shared.u64 x, %1; cvt.u32.u64 %0, x; }"
        : "=r"(a) : "l"(p));
    return a;
}

__global__ __launch_bounds__(THREADS)
void gather_wt_elem(const int* __restrict__ rel_pos,
                    const float* __restrict__ W,       // [12,64]
                    float4* __restrict__ out4)
{
    __shared__ __align__(16)  float4 table4[64 * 3];        // table4[cls*3+c]
    __shared__ __align__(128) float4 stage4[2][TILE_F4];    // 2 x 24 KB

    float* table = reinterpret_cast<float*>(table4);
    unsigned t = threadIdx.x;

    // Transposed table: table[c*12 + h] = W[h*64 + c]
    #pragma unroll
    for (int i = 0; i < 2; i++) {
        unsigned j = t + i * (unsigned)THREADS;   // [0,1024)
        if (j < 768u)
            table[(j & 63u) * 12u + (j >> 6)] = W[j];
    }
    __syncthreads();

    unsigned elem0 = blockIdx.x * (unsigned)(TILE_ELEM * TILES_PER_CTA);

    #pragma unroll
    for (int it = 0; it < TILES_PER_CTA; it++) {
        int buf = it & 1;
        unsigned ebase = elem0 + (unsigned)it * (unsigned)TILE_ELEM;

        // Before reusing a buffer, ensure its previous bulk store drained.
        if (it >= 2) {
            if (t == 0)
                asm volatile("cp.async.bulk.wait_group 1;" ::: "memory");
            __syncthreads();
        }

        // One element per thread: 1 LDG, 3 row-contiguous LDS.128,
        // 3 conflict-free stride-3 STS.128.
        {
            int cls = rel_pos[ebase + t];
            unsigned r = (unsigned)cls * 3u;
            float4 v0 = table4[r + 0];
            float4 v1 = table4[r + 1];
            float4 v2 = table4[r + 2];
            unsigned s = t * 3u;
            stage4[buf][s + 0] = v0;
            stage4[buf][s + 1] = v1;
            stage4[buf][s + 2] = v2;
        }
        __syncthreads();

        // Async bulk store: 24 KB smem -> gmem.
        if (t == 0) {
            unsigned saddr = smem_u32(stage4[buf]);
            unsigned long long gaddr =
                (unsigned long long)(out4 + (size_t)ebase * 3u);
            asm volatile("fence.proxy.async;" ::: "memory");
            asm volatile("cp.async.bulk.global.shared::cta.bulk_group [%0], [%1], %2;"
                         :: "l"(gaddr), "r"(saddr), "n"(TILE_F4 * 16) : "memory");
            asm volatile("cp.async.bulk.commit_group;" ::: "memory");
        }
        // Buffer untouched until its wait above; no extra sync needed.
    }

    // Drain before CTA exit (smem handed to next CTA).
    if (t == 0)
        asm volatile("cp.async.bulk.wait_group 0;" ::: "memory");
    __syncthreads();
}

// Generic tail (unused for the benchmark shapes): direct gather + store.
__global__ __launch_bounds__(256)
void gather_wt_tail(const int* __restrict__ rel_pos,
                    const float* __restrict__ W,
                    float4* __restrict__ out4,
                    unsigned start_elem, unsigned n_elem)
{
    __shared__ float4 table4[64 * 3];
    float* table = reinterpret_cast<float*>(table4);
    unsigned t = threadIdx.x;
    #pragma unroll
    for (int i = 0; i < 3; i++) {
        unsigned j = t + i * 256u;
        table[(j & 63u) * 12u + (j >> 6)] = W[j];
    }
    __syncthreads();

    unsigned e = start_elem + blockIdx.x * 256u + t;
    if (e < n_elem) {
        int cls = rel_pos[e];
        unsigned r = (unsigned)cls * 3u;
        size_t o = (size_t)e * 3u;
        out4[o + 0] = table4[r + 0];
        out4[o + 1] = table4[r + 1];
        out4[o + 2] = table4[r + 2];
    }
}

extern "C" void kernel_launch(void* const* d_in, const int* in_sizes, int n_in,
                              void* d_out, int out_size)
{
    const int*   rel_pos = (const int*)d_in[0];    // [4,2048,2048] int32
    // d_in[1] = hidden_states (unused; dtype carrier only)
    const float* W       = (const float*)d_in[2];  // [12,64] float32
    float4*      out4    = (float4*)d_out;

    unsigned n_elem  = (unsigned)in_sizes[0];      // 16,777,216
    unsigned per_cta = (unsigned)(TILE_ELEM * TILES_PER_CTA);  // 4096 elements
    unsigned blocks  = n_elem / per_cta;           // 4096 exact for bench
    unsigned done    = blocks * per_cta;

    if (blocks)
        gather_wt_elem<<<blocks, THREADS>>>(rel_pos, W, out4);

    if (done < n_elem) {
        unsigned rem = n_elem - done;
        unsigned tb  = (rem + 255u) / 256u;
        gather_wt_tail<<<tb, 256>>>(rel_pos, W, out4, done, n_elem);
    }
}